// round 16
// baseline (speedup 1.0000x reference)
#include <cuda_runtime.h>
#include <cuda_fp16.h>
#include <math.h>
#include <stdint.h>

#define Bx 512
#define Tt 256
#define Ii 128
#define Hh 512
#define G3 1536
#define BT (Bx * Tt)
#define NBLK 128   // 4 b-tiles(128) x 32 j-tiles(16); 1 CTA/SM, <=148 SMs

// ---------------- scratch (device globals; no allocation allowed) ----------------
__device__ float g_xg[(size_t)Tt * (size_t)Bx * (size_t)G3]; // [T][B][3H] fp32
__device__ float g_h[2][Bx * Hh];                            // fp32 hidden, ping-pong
__device__ __half g_hhi[2][Bx * Hh];                         // h fp16 hi (perm-k)
__device__ __half g_Whi[(size_t)G3 * Hh];                    // W_hh fp16 hi (perm-k)
__device__ __half g_Wlo[(size_t)G3 * Hh];                    // W_hh fp16 lo (perm-k)
__device__ __half g_xhi[(size_t)BT * Ii];                    // x fp16 hi (perm-k)
__device__ __half g_Wihhi[(size_t)G3 * Ii];                  // W_ih fp16 hi (perm-k)
__device__ __half g_Wihlo[(size_t)G3 * Ii];                  // W_ih fp16 lo (perm-k)
__device__ unsigned g_bar_cnt;
__device__ volatile unsigned g_bar_gen;

// permutation within each 16-k block so mma fragment (k, k+1, k+8, k+9) is one LDS.64
__device__ __forceinline__ int kperm(int k) {
    return ((k & 7) >> 1) * 4 + (k & 1) + (((k >> 3) & 1) << 1);
}

// ---------------- init: zero h0 + barrier state (every launch) -------------------
__global__ void init_kernel() {
    int i = blockIdx.x * 256 + threadIdx.x;
    if (i < Bx * Hh) {
        g_h[0][i] = 0.0f;
        g_hhi[0][i] = __float2half(0.0f);
    }
    if (i == 0) { g_bar_cnt = 0u; g_bar_gen = 0u; }
}

// ---------------- W_hh -> split fp16 (hi + lo), permuted-k layout ----------------
__global__ void wconv_kernel(const float* __restrict__ Whh) {
    int idx = blockIdx.x * 256 + threadIdx.x;
    if (idx >= G3 * Hh) return;
    int row = idx >> 9, k = idx & 511;
    float w = Whh[idx];
    __half hi = __float2half(w);
    float lo = w - __half2float(hi);
    int kk = (k & ~15) + kperm(k & 15);
    g_Whi[(size_t)row * Hh + kk] = hi;
    g_Wlo[(size_t)row * Hh + kk] = __float2half(lo);
}

// ---------------- x -> fp16 hi (perm-k); W_ih -> fp16 hi+lo (perm-k) -------------
__global__ void xconv_kernel(const float* __restrict__ x) {
    size_t idx = (size_t)blockIdx.x * 256 + threadIdx.x;
    if (idx >= (size_t)BT * Ii) return;
    int k = (int)(idx & (Ii - 1));
    size_t row = idx >> 7;
    int kk = (k & ~15) + kperm(k & 15);
    g_xhi[row * Ii + kk] = __float2half(x[idx]);
}
__global__ void wihconv_kernel(const float* __restrict__ Wih) {
    int idx = blockIdx.x * 256 + threadIdx.x;
    if (idx >= G3 * Ii) return;
    int row = idx >> 7, k = idx & (Ii - 1);
    float w = Wih[idx];
    __half hi = __float2half(w);
    float lo = w - __half2float(hi);
    int kk = (k & ~15) + kperm(k & 15);
    g_Wihhi[(size_t)row * Ii + kk] = hi;
    g_Wihlo[(size_t)row * Ii + kk] = __float2half(lo);
}

// ---------------- fp16 mma.sync helper -------------------------------------------
__device__ __forceinline__ void mma_f16(float* c,
    uint32_t a0, uint32_t a1, uint32_t a2, uint32_t a3,
    uint32_t b0, uint32_t b1)
{
    asm volatile(
        "mma.sync.aligned.m16n8k16.row.col.f32.f16.f16.f32 "
        "{%0,%1,%2,%3},{%4,%5,%6,%7},{%8,%9},{%0,%1,%2,%3};"
        : "+f"(c[0]), "+f"(c[1]), "+f"(c[2]), "+f"(c[3])
        : "r"(a0), "r"(a1), "r"(a2), "r"(a3), "r"(b0), "r"(b1));
}

// ---------------- kernel 1: xg via fp16 MMA (2-term split) -----------------------
#define XAST 80
__global__ __launch_bounds__(256) void xg_mma_kernel(
    const float* __restrict__ bih, const float* __restrict__ bhh)
{
    __shared__ __half As[64 * XAST];
    __shared__ __half Bh[64 * XAST];
    __shared__ __half Bl[64 * XAST];

    const int tid  = threadIdx.x;
    const int lane = tid & 31;
    const int w    = tid >> 5;
    const int mt   = w >> 1, jp = w & 1;
    const int qrow = lane >> 2, qcol = lane & 3;

    const int bt0 = blockIdx.x * 64;
    const int n0  = blockIdx.y * 64;

    const int sr  = tid >> 3;     // 0..31
    const int pos = tid & 7;

    float acc[4][4];
#pragma unroll
    for (int nt = 0; nt < 4; ++nt)
#pragma unroll
        for (int e = 0; e < 4; ++e) acc[nt][e] = 0.0f;

    const int ar0 = mt * 16 + qrow, ar8 = ar0 + 8;

#pragma unroll
    for (int ch = 0; ch < 2; ++ch) {
        const int kb = ch * 64;
        __syncthreads();            // prior chunk consumed
#pragma unroll
        for (int i = 0; i < 2; ++i) {
            int r = sr + 32 * i;
            *(uint4*)&As[r * XAST + pos * 8] =
                *(const uint4*)(g_xhi + (size_t)(bt0 + r) * Ii + kb + pos * 8);
            size_t goff = (size_t)(n0 + r) * Ii + kb + pos * 8;
            *(uint4*)&Bh[r * XAST + pos * 8] = *(const uint4*)(g_Wihhi + goff);
            *(uint4*)&Bl[r * XAST + pos * 8] = *(const uint4*)(g_Wihlo + goff);
        }
        __syncthreads();
#pragma unroll
        for (int kt = 0; kt < 4; ++kt) {
            const int aoff = kt * 16 + qcol * 4;
            uint2 a0 = *(const uint2*)&As[ar0 * XAST + aoff];
            uint2 a8 = *(const uint2*)&As[ar8 * XAST + aoff];
            uint2 bh[4], bl[4];
#pragma unroll
            for (int nt = 0; nt < 4; ++nt) {
                int brow = jp * 32 + nt * 8 + qrow;
                bh[nt] = *(const uint2*)&Bh[brow * XAST + aoff];
                bl[nt] = *(const uint2*)&Bl[brow * XAST + aoff];
            }
#pragma unroll
            for (int nt = 0; nt < 4; ++nt)
                mma_f16(acc[nt], a0.x, a8.x, a0.y, a8.y, bh[nt].x, bh[nt].y);
#pragma unroll
            for (int nt = 0; nt < 4; ++nt)
                mma_f16(acc[nt], a0.x, a8.x, a0.y, a8.y, bl[nt].x, bl[nt].y);
        }
    }

#pragma unroll
    for (int nt = 0; nt < 4; ++nt)
#pragma unroll
        for (int e = 0; e < 4; ++e) {
            int bt = bt0 + mt * 16 + qrow + ((e >> 1) ? 8 : 0);
            int col = n0 + jp * 32 + nt * 8 + qcol * 2 + (e & 1);
            int b = bt / Tt, t = bt % Tt;      // x rows are [B][T]
            float bias = bih[col] + (col < 2 * Hh ? bhh[col] : 0.0f);
            g_xg[((size_t)t * Bx + b) * G3 + col] = acc[nt][e] + bias;
        }
}

// ---------------- persistent GRU smem layout (halves) ----------------------------
// W resident: 48 rows (3 gates x 16 j) x 512 k, stride 520 (bank-safe), hi + lo.
// A staging: 2 stages x 128 rows x 64 k, stride 80.
#define WST 520
#define AST 80
#define OFF_WHI 0
#define OFF_WLO (48 * WST)                 // 24960
#define OFF_A   (2 * 48 * WST)             // 49920
#define A_STAGE (128 * AST)                // 10240
#define SMEM_HALVES (OFF_A + 2 * A_STAGE)  // 70400
#define SMEM_BYTES (SMEM_HALVES * 2)       // 140800

// ---------------- grid barrier (128 co-resident CTAs; proven in R9) --------------
__device__ __forceinline__ void gridbar() {
    __syncthreads();
    if (threadIdx.x == 0) {
        __threadfence();
        unsigned gen = g_bar_gen;
        if (atomicAdd(&g_bar_cnt, 1u) == NBLK - 1u) {
            g_bar_cnt = 0u;
            __threadfence();
            g_bar_gen = gen + 1u;
        } else {
            while (g_bar_gen == gen) __nanosleep(64);
        }
        __threadfence();
    }
    __syncthreads();
}

// ---------------- kernel 2: persistent GRU, W SMEM-resident ----------------------
// Block = 128 batch rows x 16 j-cols (all 3 gates). W hi/lo loaded to SMEM once;
// per step only A (h fp16) is staged (double-buffered LDG->reg->STS, __ldcg for
// cross-block coherence). Term-major fp16 MMA, fused gate epilogue, gridbar/step.
__global__ __launch_bounds__(256, 1) void gru_persist_kernel(
    const float* __restrict__ bhh)
{
    extern __shared__ __half sm[];
    __half* Wh = sm + OFF_WHI;
    __half* Wl = sm + OFF_WLO;

    const int tid  = threadIdx.x;
    const int lane = tid & 31;
    const int w    = tid >> 5;          // 8 warps; warp w owns rows [w*16, w*16+16)
    const int qrow = lane >> 2;
    const int qcol = lane & 3;

    const int b0 = (blockIdx.x >> 5) * 128;   // 4 b-tiles
    const int j0 = (blockIdx.x & 31) * 16;    // 32 j-tiles

    // ---- load W slice into SMEM once (48 rows x 512 halves, hi + lo) ----
    {
        int r = tid >> 3, pos = tid & 7;      // 32 rows/pass, 8 x 64-halves slots
        for (int i = 0; i < 2; ++i) {
            int p = r + 32 * i;
            if (p < 48) {
                int grow = (p >> 4) * Hh + j0 + (p & 15);
                for (int s = 0; s < 8; ++s) {
                    int kk = s * 64 + pos * 8;
                    *(uint4*)&Wh[p * WST + kk] =
                        *(const uint4*)(g_Whi + (size_t)grow * Hh + kk);
                    *(uint4*)&Wl[p * WST + kk] =
                        *(const uint4*)(g_Wlo + (size_t)grow * Hh + kk);
                }
            }
        }
    }
    __syncthreads();

    // staging decomposition for A (128 rows x 64 halves per chunk)
    const int sr  = tid >> 3;           // 0..31 (+32i)
    const int pos = tid & 7;

    const int ar0 = w * 16 + qrow, ar8 = ar0 + 8;

    // epilogue coordinates (constant across steps)
    int erow[2][4], ej[2][4];
    float pre_bn[2][4];
#pragma unroll
    for (int nt = 0; nt < 2; ++nt)
#pragma unroll
        for (int e = 0; e < 4; ++e) {
            erow[nt][e] = b0 + w * 16 + qrow + ((e >> 1) ? 8 : 0);
            ej[nt][e]   = j0 + nt * 8 + qcol * 2 + (e & 1);
            pre_bn[nt][e] = bhh[2 * Hh + ej[nt][e]];
        }

    uint4 ra[4];                        // in-flight A chunk (4 x 16B per thread)

#pragma unroll 1
    for (int t = 0; t < Tt; ++t) {
        const __half* hhi_in = g_hhi[t & 1];
        const float* hf_in = g_h[t & 1];
        float* hf_out = g_h[(t + 1) & 1];
        __half* hhi_out = g_hhi[(t + 1) & 1];

        auto load_regs = [&](int ch) {
            const int kb = ch * 64;
#pragma unroll
            for (int i = 0; i < 4; ++i) {
                int r = sr + 32 * i;
                ra[i] = __ldcg((const uint4*)(hhi_in + (size_t)(b0 + r) * Hh + kb + pos * 8));
            }
        };
        auto sts_regs = [&](int s) {
            __half* st = sm + OFF_A + s * A_STAGE;
#pragma unroll
            for (int i = 0; i < 4; ++i) {
                int r = sr + 32 * i;
                *(uint4*)&st[r * AST + pos * 8] = ra[i];
            }
        };

        // epilogue operand prefetch (xg write-once; h_prev post-gridbar -> safe)
        float pxr[2][4], pxz[2][4], pxn[2][4], ph[2][4];
        const float* xg_t = g_xg + (size_t)t * Bx * G3;
#pragma unroll
        for (int nt = 0; nt < 2; ++nt)
#pragma unroll
            for (int e = 0; e < 4; ++e) {
                const float* xp = xg_t + (size_t)erow[nt][e] * G3 + ej[nt][e];
                pxr[nt][e] = xp[0];
                pxz[nt][e] = xp[Hh];
                pxn[nt][e] = xp[2 * Hh];
                ph[nt][e]  = __ldcg(hf_in + (size_t)erow[nt][e] * Hh + ej[nt][e]);
            }

        load_regs(0);
        sts_regs(0);
        load_regs(1);
        __syncthreads();    // stage0 published

        float acc[3][2][4];
#pragma unroll
        for (int g = 0; g < 3; ++g)
#pragma unroll
            for (int nt = 0; nt < 2; ++nt)
#pragma unroll
                for (int e = 0; e < 4; ++e) acc[g][nt][e] = 0.0f;

#pragma unroll 1
        for (int ch = 0; ch < 8; ++ch) {
            if (ch < 7) sts_regs((ch + 1) & 1);
            if (ch < 6) load_regs(ch + 2);

            const __half* As = sm + OFF_A + (ch & 1) * A_STAGE;
            const int kb = ch * 64;

#pragma unroll
            for (int kt = 0; kt < 4; ++kt) {
                const int aoff = kt * 16 + qcol * 4;
                uint2 a0 = *(const uint2*)&As[ar0 * AST + aoff];
                uint2 a8 = *(const uint2*)&As[ar8 * AST + aoff];
                const int woff = kb + kt * 16 + qcol * 4;
                uint2 bh[3][2], bl[3][2];
#pragma unroll
                for (int g = 0; g < 3; ++g)
#pragma unroll
                    for (int nt = 0; nt < 2; ++nt) {
                        int brow = g * 16 + nt * 8 + qrow;
                        bh[g][nt] = *(const uint2*)&Wh[brow * WST + woff];
                        bl[g][nt] = *(const uint2*)&Wl[brow * WST + woff];
                    }
                // term-major: 6 independent accumulators between same-acc MMAs
#pragma unroll
                for (int g = 0; g < 3; ++g)
#pragma unroll
                    for (int nt = 0; nt < 2; ++nt)
                        mma_f16(acc[g][nt], a0.x, a8.x, a0.y, a8.y,
                                bh[g][nt].x, bh[g][nt].y);
#pragma unroll
                for (int g = 0; g < 3; ++g)
#pragma unroll
                    for (int nt = 0; nt < 2; ++nt)
                        mma_f16(acc[g][nt], a0.x, a8.x, a0.y, a8.y,
                                bl[g][nt].x, bl[g][nt].y);
            }
            if (ch < 7) __syncthreads();
        }

        // -------- epilogue: gates fused in registers --------
#pragma unroll
        for (int nt = 0; nt < 2; ++nt)
#pragma unroll
            for (int e = 0; e < 4; ++e) {
                int row = erow[nt][e], j = ej[nt][e];
                float hr = acc[0][nt][e];
                float hz = acc[1][nt][e];
                float hn = acc[2][nt][e] + pre_bn[nt][e];   // b_hh_n inside r*hn
                float r = 1.0f / (1.0f + expf(-(pxr[nt][e] + hr)));
                float z = 1.0f / (1.0f + expf(-(pxz[nt][e] + hz)));
                float n = tanhf(pxn[nt][e] + r * hn);
                float hnew = (1.0f - z) * n + z * ph[nt][e];
                hf_out[row * Hh + j] = hnew;
                int jj = (j & ~15) + kperm(j & 15);
                hhi_out[row * Hh + jj] = __float2half(hnew);
            }

        gridbar();
    }
}

// ---------------- kernel 3: out[b] = h_T[b,:] @ W_lin + b_lin -------------------
__global__ void out_kernel(const float* __restrict__ Wlin,
                           const float* __restrict__ blin,
                           float* __restrict__ out)
{
    int w = (blockIdx.x * blockDim.x + threadIdx.x) >> 5;
    int lane = threadIdx.x & 31;
    if (w >= Bx) return;
    const float* h = g_h[0] + (size_t)w * Hh;   // T=256 even -> final in buf 0
    float s = 0.0f;
#pragma unroll
    for (int i = 0; i < Hh / 32; ++i) s += h[lane + 32 * i] * Wlin[lane + 32 * i];
#pragma unroll
    for (int o = 16; o; o >>= 1) s += __shfl_xor_sync(0xffffffffu, s, o);
    if (lane == 0) out[w] = s + blin[0];
}

// ---------------- launch ---------------------------------------------------------
extern "C" void kernel_launch(void* const* d_in, const int* in_sizes, int n_in,
                              void* d_out, int out_size)
{
    const float* x    = (const float*)d_in[0];
    const float* Wih  = (const float*)d_in[1];
    const float* Whh  = (const float*)d_in[2];
    const float* bih  = (const float*)d_in[3];
    const float* bhh  = (const float*)d_in[4];
    const float* Wlin = (const float*)d_in[5];
    const float* blin = (const float*)d_in[6];
    float* out = (float*)d_out;

    cudaFuncSetAttribute(gru_persist_kernel,
                         cudaFuncAttributeMaxDynamicSharedMemorySize, SMEM_BYTES);

    init_kernel<<<(Bx * Hh + 255) / 256, 256>>>();
    wconv_kernel<<<(G3 * Hh + 255) / 256, 256>>>(Whh);
    xconv_kernel<<<(int)(((size_t)BT * Ii + 255) / 256), 256>>>(x);
    wihconv_kernel<<<(G3 * Ii + 255) / 256, 256>>>(Wih);
    dim3 gx(BT / 64, G3 / 64);
    xg_mma_kernel<<<gx, 256>>>(bih, bhh);
    gru_persist_kernel<<<NBLK, 256, SMEM_BYTES>>>(bhh);
    out_kernel<<<(Bx * 32) / 256, 256>>>(Wlin, blin, out);
}